// round 9
// baseline (speedup 1.0000x reference)
#include <cuda_runtime.h>
#include <cstdint>

#define VOCAB 100000
#define DIM   300
#define BATCH 65536
#define KNEG  10
#define NF4   75            // DIM/4 float4 per row
#define ROWF4S 80           // padded row stride in float4 (1280B)
#define WARPS_PER_BLOCK 8
#define THREADS (WARPS_PER_BLOCK * 32)
#define DEPTH 2
#define GRIDB (148 * 8)                     // 1184 blocks, one full wave at occ 8
#define TOTWARPS (GRIDB * WARPS_PER_BLOCK)  // 9472 persistent warps

__device__ float g_partials[GRIDB];
__device__ unsigned int g_count;    // zero-init; last block resets after use

__device__ __forceinline__ float softplus_fast(float x) {
    return __logf(1.0f + __expf(x));   // valid for clipped |x| <= 10
}

__device__ __forceinline__ void cp_async16(uint32_t saddr, const void* gptr) {
    asm volatile("cp.async.cg.shared.global [%0], [%1], 16;" :: "r"(saddr), "l"(gptr));
}
__device__ __forceinline__ void cp_commit() {
    asm volatile("cp.async.commit_group;" ::: "memory");
}
template <int N>
__device__ __forceinline__ void cp_wait() {
    asm volatile("cp.async.wait_group %0;" :: "n"(N) : "memory");
}

// lanes 0..9 -> neg_v[s*10+lane]; lane 10 -> pos_v[s]
__device__ __forceinline__ int load_vidx(const int* __restrict__ neg_v,
                                         const int* __restrict__ pos_v,
                                         int s, int lane) {
    int r = 0;
    if (lane < KNEG)       r = neg_v[s * KNEG + lane];
    else if (lane == KNEG) r = pos_v[s];
    return r;
}

__global__ __launch_bounds__(THREADS, 8)
void sg_loss_kernel(const float* __restrict__ u_w,
                    const float* __restrict__ v_w,
                    const int*   __restrict__ pos_u,
                    const int*   __restrict__ pos_v,
                    const int*   __restrict__ neg_v,
                    float* __restrict__ out) {
    __shared__ float4 vbuf[WARPS_PER_BLOCK][DEPTH][ROWF4S];   // 20480 B
    const int warp = threadIdx.x >> 5;
    const int lane = threadIdx.x & 31;
    const int gw = blockIdx.x * WARPS_PER_BLOCK + warp;

    const bool has2 = lane < (NF4 - 64);   // lanes 0..10 hold the 3rd float4

    // per-lane smem addresses for the two ring slots (this lane's own chunks)
    uint32_t sa[DEPTH][3];
#pragma unroll
    for (int d = 0; d < DEPTH; d++) {
        sa[d][0] = (uint32_t)__cvta_generic_to_shared(&vbuf[warp][d][lane]);
        sa[d][1] = (uint32_t)__cvta_generic_to_shared(&vbuf[warp][d][lane + 32]);
        sa[d][2] = (uint32_t)__cvta_generic_to_shared(&vbuf[warp][d][lane + 64]);
    }

    float acc = 0.f;

    int s = gw;
    int vpack = 0, pu = 0;
    if (s < BATCH) {
        vpack = load_vidx(neg_v, pos_v, s, lane);
        pu = pos_u[s];
    }

    while (s < BATCH) {
        const int snext = s + TOTWARPS;

        // row r of this sample: r==0 -> pos_v (lane KNEG), else neg (lane r-1)
        // helper to compute row base pointer:
        // (indices broadcast from vpack)
#define ROWPTR(r) (reinterpret_cast<const float4*>( \
            v_w + (long long)__shfl_sync(0xffffffffu, vpack, ((r) == 0) ? KNEG : ((r) - 1)) * DIM))

#define PREFETCH(r) do {                                             \
            const float4* _vr = ROWPTR(r);                           \
            const int _d = (r) & 1;                                  \
            cp_async16(sa[_d][0], _vr + lane);                       \
            cp_async16(sa[_d][1], _vr + lane + 32);                  \
            if (has2) cp_async16(sa[_d][2], _vr + lane + 64);        \
            cp_commit();                                             \
        } while (0)

        // ---- issue u gather (regs) + rows 0,1 (smem); waits overlap ----
        const float4* u_row = reinterpret_cast<const float4*>(u_w + (long long)pu * DIM);
        PREFETCH(0);
        PREFETCH(1);
        const float4 u0 = __ldcs(u_row + lane);
        const float4 u1 = __ldcs(u_row + lane + 32);
        float4 u2 = make_float4(0.f, 0.f, 0.f, 0.f);
        if (has2) u2 = __ldcs(u_row + lane + 64);

        // ---- software-pipeline: fetch NEXT sample's indices now ----
        int vpack_n = 0, pu_n = 0;
        if (snext < BATCH) {
            vpack_n = load_vidx(neg_v, pos_v, snext, lane);
            pu_n = pos_u[snext];
        }

        // ---- process 11 rows in batches of 4/4/3 ----
#define DOROW(r, pdst) do {                                          \
            if ((r) == 10) cp_wait<0>(); else cp_wait<1>();          \
            const int _d = (r) & 1;                                  \
            const float4 v0 = vbuf[warp][_d][lane];                  \
            const float4 v1 = vbuf[warp][_d][lane + 32];             \
            float4 v2 = make_float4(0.f, 0.f, 0.f, 0.f);             \
            if (has2) v2 = vbuf[warp][_d][lane + 64];                \
            float _a = u0.x * v0.x;                                  \
            _a = fmaf(u0.y, v0.y, _a); _a = fmaf(u0.z, v0.z, _a);    \
            _a = fmaf(u0.w, v0.w, _a);                               \
            float _c = u1.x * v1.x;                                  \
            _c = fmaf(u1.y, v1.y, _c); _c = fmaf(u1.z, v1.z, _c);    \
            _c = fmaf(u1.w, v1.w, _c);                               \
            float _e = u2.x * v2.x;                                  \
            _e = fmaf(u2.y, v2.y, _e); _e = fmaf(u2.z, v2.z, _e);    \
            _e = fmaf(u2.w, v2.w, _e);                               \
            pdst = (_a + _c) + _e;                                   \
            if ((r) + 2 <= 10) PREFETCH((r) + 2);                    \
        } while (0)

        {   // rows 0..3 (row 0 = positive)
            float p0, p1, p2, p3;
            DOROW(0, p0); DOROW(1, p1); DOROW(2, p2); DOROW(3, p3);
#pragma unroll
            for (int off = 16; off; off >>= 1) {
                p0 += __shfl_xor_sync(0xffffffffu, p0, off);
                p1 += __shfl_xor_sync(0xffffffffu, p1, off);
                p2 += __shfl_xor_sync(0xffffffffu, p2, off);
                p3 += __shfl_xor_sync(0xffffffffu, p3, off);
            }
            float sel = (lane == 0) ? p0 : (lane == 1) ? p1 : (lane == 2) ? p2 : p3;
            if (lane < 4) {
                float sc = fminf(fmaxf(sel, -10.f), 10.f);
                acc += softplus_fast((lane == 0) ? -sc : sc);
            }
        }
        {   // rows 4..7
            float p0, p1, p2, p3;
            DOROW(4, p0); DOROW(5, p1); DOROW(6, p2); DOROW(7, p3);
#pragma unroll
            for (int off = 16; off; off >>= 1) {
                p0 += __shfl_xor_sync(0xffffffffu, p0, off);
                p1 += __shfl_xor_sync(0xffffffffu, p1, off);
                p2 += __shfl_xor_sync(0xffffffffu, p2, off);
                p3 += __shfl_xor_sync(0xffffffffu, p3, off);
            }
            float sel = (lane == 0) ? p0 : (lane == 1) ? p1 : (lane == 2) ? p2 : p3;
            if (lane < 4) {
                float sc = fminf(fmaxf(sel, -10.f), 10.f);
                acc += softplus_fast(sc);
            }
        }
        {   // rows 8..10
            float p0, p1, p2;
            DOROW(8, p0); DOROW(9, p1); DOROW(10, p2);
#pragma unroll
            for (int off = 16; off; off >>= 1) {
                p0 += __shfl_xor_sync(0xffffffffu, p0, off);
                p1 += __shfl_xor_sync(0xffffffffu, p1, off);
                p2 += __shfl_xor_sync(0xffffffffu, p2, off);
            }
            float sel = (lane == 0) ? p0 : (lane == 1) ? p1 : p2;
            if (lane < 3) {
                float sc = fminf(fmaxf(sel, -10.f), 10.f);
                acc += softplus_fast(sc);
            }
        }
#undef DOROW
#undef PREFETCH
#undef ROWPTR

        s = snext; vpack = vpack_n; pu = pu_n;
    }

    // ---- one final warp reduction over the per-lane accumulators ----
#pragma unroll
    for (int off = 16; off; off >>= 1)
        acc += __shfl_xor_sync(0xffffffffu, acc, off);

    __shared__ float sloss[WARPS_PER_BLOCK];
    if (lane == 0) sloss[warp] = acc;
    __syncthreads();

    __shared__ unsigned s_is_last;
    if (threadIdx.x == 0) {
        float t = 0.f;
#pragma unroll
        for (int i = 0; i < WARPS_PER_BLOCK; i++) t += sloss[i];
        g_partials[blockIdx.x] = t;
        __threadfence();
        unsigned prev = atomicAdd(&g_count, 1u);
        s_is_last = (prev == (unsigned)(gridDim.x - 1));
    }
    __syncthreads();

    // ---- last block reduces all partials (deterministic fixed order) ----
    if (s_is_last) {
        __threadfence();
        float t = 0.f;
        for (int i = threadIdx.x; i < GRIDB; i += THREADS) t += g_partials[i];
#pragma unroll
        for (int off = 16; off; off >>= 1)
            t += __shfl_xor_sync(0xffffffffu, t, off);

        __shared__ float sred[WARPS_PER_BLOCK];
        if (lane == 0) sred[warp] = t;
        __syncthreads();
        if (threadIdx.x == 0) {
            float total = 0.f;
#pragma unroll
            for (int i = 0; i < WARPS_PER_BLOCK; i++) total += sred[i];
            out[0] = total * (1.0f / (float)BATCH);
            g_count = 0;   // reset for next graph replay
        }
    }
}

extern "C" void kernel_launch(void* const* d_in, const int* in_sizes, int n_in,
                              void* d_out, int out_size) {
    const float* u_w   = (const float*)d_in[0];
    const float* v_w   = (const float*)d_in[1];
    const int*   pos_u = (const int*)  d_in[2];
    const int*   pos_v = (const int*)  d_in[3];
    const int*   neg_v = (const int*)  d_in[4];
    float* out = (float*)d_out;

    sg_loss_kernel<<<GRIDB, THREADS>>>(u_w, v_w, pos_u, pos_v, neg_v, out);
}